// round 1
// baseline (speedup 1.0000x reference)
#include <cuda_runtime.h>
#include <cuda_bf16.h>
#include <math.h>

#define NB 8
#define LL 512
#define EE 768
#define HH 12
#define DD 64
#define MPOS 1023   // 2*512-1

// ---------------- scratch (static device allocations; no cudaMalloc) ----------------
__device__ float g_pe[MPOS * EE];          // sinusoid table
__device__ float g_R [MPOS * EE];          // pe @ Wpos + bpos
__device__ float g_q [NB * LL * EE];       // query proj  [n][l][h*64+d]
__device__ float g_k [NB * LL * EE];
__device__ float g_v [NB * LL * EE];
__device__ float g_s [(size_t)NB * HH * LL * LL]; // scores -> attn (in place)
__device__ float g_o [NB * LL * EE];       // attn @ v, [n][l][h*64+d]

// ---------------- sinusoid table ----------------
__global__ void pe_kernel() {
    int i = blockIdx.x * blockDim.x + threadIdx.x;
    if (i >= MPOS * (EE / 2)) return;
    int p = i / (EE / 2);
    int m = i % (EE / 2);
    float div = __expf((float)(2 * m) * (-9.210340371976184f / (float)EE));
    float ang = (float)p * div;
    float s, c;
    __sincosf(ang, &s, &c);
    // __sincosf is fast-math; use accurate version for safety:
    s = sinf(ang); c = cosf(ang);
    g_pe[p * EE + 2 * m]     = s;
    g_pe[p * EE + 2 * m + 1] = c;
}

// ---------------- generic tiled SGEMM: C[M,N] = A[M,K] @ B[K,N] + bias[N] ----------------
// 64x64 tile, K-chunk 16, 256 threads, 4x4 per thread.
__global__ void sgemm_bias(const float* __restrict__ A, const float* __restrict__ B,
                           const float* __restrict__ bias, float* __restrict__ C,
                           int M, int Nn, int K) {
    __shared__ float As[16][65];
    __shared__ float Bs[16][65];
    int t  = threadIdx.x;
    int m0 = blockIdx.y * 64;
    int n0 = blockIdx.x * 64;
    int tx = t & 15, ty = t >> 4;
    float acc[4][4] = {};
    for (int k0 = 0; k0 < K; k0 += 16) {
        #pragma unroll
        for (int i = t; i < 64 * 16; i += 256) {
            int m = i >> 4, kk = i & 15;
            As[kk][m] = (m0 + m < M) ? A[(size_t)(m0 + m) * K + k0 + kk] : 0.f;
        }
        #pragma unroll
        for (int i = t; i < 16 * 64; i += 256) {
            int kk = i >> 6, nn = i & 63;
            Bs[kk][nn] = B[(size_t)(k0 + kk) * Nn + n0 + nn];
        }
        __syncthreads();
        #pragma unroll
        for (int kk = 0; kk < 16; kk++) {
            float a[4], b[4];
            #pragma unroll
            for (int r = 0; r < 4; r++) a[r] = As[kk][ty * 4 + r];
            #pragma unroll
            for (int c = 0; c < 4; c++) b[c] = Bs[kk][tx * 4 + c];
            #pragma unroll
            for (int r = 0; r < 4; r++)
                #pragma unroll
                for (int c = 0; c < 4; c++) acc[r][c] = fmaf(a[r], b[c], acc[r][c]);
        }
        __syncthreads();
    }
    #pragma unroll
    for (int r = 0; r < 4; r++) {
        int m = m0 + ty * 4 + r;
        if (m >= M) continue;
        #pragma unroll
        for (int c = 0; c < 4; c++) {
            int nn = n0 + tx * 4 + c;
            C[(size_t)m * Nn + nn] = acc[r][c] + bias[nn];
        }
    }
}

// ---------------- fused score kernel: s = (q·(k+R) + rwb·k + rrb·R) / sqrt(D) ----------------
// grid: (L/32 k-tiles, L/32 q-tiles, N*H), 256 threads
__global__ void scores_kernel(const float* __restrict__ rwb, const float* __restrict__ rrb) {
    const int k0 = blockIdx.x * 32;
    const int q0 = blockIdx.y * 32;
    const int nh = blockIdx.z;
    const int n  = nh / HH, h = nh % HH;

    __shared__ float sq[32][65], sk[32][65], sR[63][65];
    __shared__ float kb[32], rb[63];

    const int t = threadIdx.x;
    const float* qbase = g_q + (size_t)n * LL * EE + h * DD;
    const float* kbase = g_k + (size_t)n * LL * EE + h * DD;

    for (int i = t; i < 32 * 64; i += 256) {
        int r = i >> 6, c = i & 63;
        sq[r][c] = qbase[(size_t)(q0 + r) * EE + c];
        sk[r][c] = kbase[(size_t)(k0 + r) * EE + c];
    }
    // R rows needed: (q0 - k0 + 511) + (qy - kx), qy-kx in (-32,32) -> 63 rows
    const int base = q0 - k0 + 480;   // +511 - 31
    for (int i = t; i < 63 * 64; i += 256) {
        int r = i >> 6, c = i & 63;
        sR[r][c] = g_R[(size_t)(base + r) * EE + h * DD + c];
    }
    __syncthreads();

    if (t < 32) {
        float s = 0.f;
        #pragma unroll
        for (int d = 0; d < DD; d++) s = fmaf(rwb[h * DD + d], sk[t][d], s);
        kb[t] = s;
    } else if (t < 95) {
        int r = t - 32;
        float s = 0.f;
        #pragma unroll
        for (int d = 0; d < DD; d++) s = fmaf(rrb[h * DD + d], sR[r][d], s);
        rb[r] = s;
    }
    __syncthreads();

    const int kx  = t & 31;
    const int qy0 = (t >> 5) * 4;
    float acc[4] = {0.f, 0.f, 0.f, 0.f};
    #pragma unroll 8
    for (int d = 0; d < DD; d++) {
        float kv = sk[kx][d];
        #pragma unroll
        for (int r = 0; r < 4; r++) {
            acc[r] = fmaf(sq[qy0 + r][d], kv + sR[qy0 + r - kx + 31][d], acc[r]);
        }
    }
    const float scale = 0.125f;  // 1/sqrt(64)
    float* srow = g_s + (((size_t)nh) * LL + q0) * LL + k0;
    #pragma unroll
    for (int r = 0; r < 4; r++) {
        int qy = qy0 + r;
        srow[(size_t)qy * LL + kx] = (acc[r] + kb[kx] + rb[qy - kx + 31]) * scale;
    }
}

// ---------------- softmax over k (row length 512), one warp per row ----------------
__global__ void softmax_kernel() {
    int row  = blockIdx.x * 8 + (threadIdx.x >> 5);
    int lane = threadIdx.x & 31;
    float* p = g_s + (size_t)row * LL;
    float vals[16];
    float mx = -INFINITY;
    #pragma unroll
    for (int i = 0; i < 16; i++) { vals[i] = p[lane + i * 32]; mx = fmaxf(mx, vals[i]); }
    #pragma unroll
    for (int o = 16; o; o >>= 1) mx = fmaxf(mx, __shfl_xor_sync(0xffffffffu, mx, o));
    float sum = 0.f;
    #pragma unroll
    for (int i = 0; i < 16; i++) { vals[i] = __expf(vals[i] - mx); sum += vals[i]; }
    #pragma unroll
    for (int o = 16; o; o >>= 1) sum += __shfl_xor_sync(0xffffffffu, sum, o);
    float inv = 1.f / sum;
    #pragma unroll
    for (int i = 0; i < 16; i++) p[lane + i * 32] = vals[i] * inv;
}

// ---------------- attn @ v : per (n,h), (512x512)@(512x64) ----------------
// grid: (L/64 q-tiles, N*H), 256 threads, 4x4 per thread on a 64x64 tile
__global__ void av_kernel() {
    int nh = blockIdx.y;
    int n = nh / HH, h = nh % HH;
    int q0 = blockIdx.x * 64;
    __shared__ float sA[64][33];
    __shared__ float sV[32][65];
    int t = threadIdx.x;
    int tx = t & 15, ty = t >> 4;
    float acc[4][4] = {};
    const float* A  = g_s + ((size_t)nh * LL + q0) * LL;
    const float* Vb = g_v + (size_t)n * LL * EE + h * DD;
    for (int k0 = 0; k0 < LL; k0 += 32) {
        for (int i = t; i < 64 * 32; i += 256) {
            int r = i >> 5, c = i & 31;
            sA[r][c] = A[(size_t)r * LL + k0 + c];
        }
        for (int i = t; i < 32 * 64; i += 256) {
            int r = i >> 6, c = i & 63;
            sV[r][c] = Vb[(size_t)(k0 + r) * EE + c];
        }
        __syncthreads();
        #pragma unroll
        for (int kk = 0; kk < 32; kk++) {
            float a[4], b[4];
            #pragma unroll
            for (int r = 0; r < 4; r++) a[r] = sA[ty * 4 + r][kk];
            #pragma unroll
            for (int c = 0; c < 4; c++) b[c] = sV[kk][tx * 4 + c];
            #pragma unroll
            for (int r = 0; r < 4; r++)
                #pragma unroll
                for (int c = 0; c < 4; c++) acc[r][c] = fmaf(a[r], b[c], acc[r][c]);
        }
        __syncthreads();
    }
    float* O = g_o + ((size_t)n * LL + q0) * EE + h * DD;
    #pragma unroll
    for (int r = 0; r < 4; r++)
        #pragma unroll
        for (int c = 0; c < 4; c++)
            O[(size_t)(ty * 4 + r) * EE + tx * 4 + c] = acc[r][c];
}

// ---------------- launch ----------------
extern "C" void kernel_launch(void* const* d_in, const int* in_sizes, int n_in,
                              void* d_out, int out_size) {
    const float* values = (const float*)d_in[0];
    const float* keys   = (const float*)d_in[1];
    const float* query  = (const float*)d_in[2];
    const float* Wq = (const float*)d_in[3];
    const float* bq = (const float*)d_in[4];
    const float* Wk = (const float*)d_in[5];
    const float* bk = (const float*)d_in[6];
    const float* Wv = (const float*)d_in[7];
    const float* bv = (const float*)d_in[8];
    const float* Wo = (const float*)d_in[9];
    const float* bo = (const float*)d_in[10];
    const float* Wpos = (const float*)d_in[11];
    const float* bpos = (const float*)d_in[12];
    const float* rwb  = (const float*)d_in[13];
    const float* rrb  = (const float*)d_in[14];
    float* out = (float*)d_out;

    float* pe_ptr; cudaGetSymbolAddress((void**)&pe_ptr, g_pe);
    float* R_ptr;  cudaGetSymbolAddress((void**)&R_ptr,  g_R);
    float* q_ptr;  cudaGetSymbolAddress((void**)&q_ptr,  g_q);
    float* k_ptr;  cudaGetSymbolAddress((void**)&k_ptr,  g_k);
    float* v_ptr;  cudaGetSymbolAddress((void**)&v_ptr,  g_v);
    float* o_ptr;  cudaGetSymbolAddress((void**)&o_ptr,  g_o);

    const int M = NB * LL;  // 4096

    // 1. sinusoid table
    pe_kernel<<<(MPOS * (EE / 2) + 255) / 256, 256>>>();

    // 2. R = pe @ Wpos + bpos   (1023 x 768)
    sgemm_bias<<<dim3(EE / 64, (MPOS + 63) / 64), 256>>>(pe_ptr, Wpos, bpos, R_ptr, MPOS, EE, EE);

    // 3-5. projections (4096 x 768 each)
    sgemm_bias<<<dim3(EE / 64, M / 64), 256>>>(query,  Wq, bq, q_ptr, M, EE, EE);
    sgemm_bias<<<dim3(EE / 64, M / 64), 256>>>(keys,   Wk, bk, k_ptr, M, EE, EE);
    sgemm_bias<<<dim3(EE / 64, M / 64), 256>>>(values, Wv, bv, v_ptr, M, EE, EE);

    // 6. fused relative-position scores
    scores_kernel<<<dim3(LL / 32, LL / 32, NB * HH), 256>>>(rwb, rrb);

    // 7. softmax
    softmax_kernel<<<(NB * HH * LL) / 8, 256>>>();

    // 8. attn @ v
    av_kernel<<<dim3(LL / 64, NB * HH), 256>>>();

    // 9. output projection -> d_out
    sgemm_bias<<<dim3(EE / 64, M / 64), 256>>>(o_ptr, Wo, bo, out, M, EE, EE);
}

// round 2
// speedup vs baseline: 1.7279x; 1.7279x over previous
#include <cuda_runtime.h>
#include <cuda_bf16.h>
#include <math.h>

#define NB 8
#define LL 512
#define EE 768
#define HH 12
#define DD 64
#define MPOS 1023   // 2*512-1

// ---------------- scratch ----------------
__device__ float g_pe[MPOS * EE];
__device__ float g_R [MPOS * EE];
__device__ float g_q [NB * LL * EE];
__device__ float g_k [NB * LL * EE];
__device__ float g_v [NB * LL * EE];
__device__ float g_s [(size_t)NB * HH * LL * LL];
__device__ float g_o [NB * LL * EE];

// ---------------- sinusoid table ----------------
__global__ void pe_kernel() {
    int i = blockIdx.x * blockDim.x + threadIdx.x;
    if (i >= MPOS * (EE / 2)) return;
    int p = i / (EE / 2);
    int m = i % (EE / 2);
    float div = expf((float)(2 * m) * (-9.210340371976184f / (float)EE));
    float ang = (float)p * div;
    g_pe[p * EE + 2 * m]     = sinf(ang);
    g_pe[p * EE + 2 * m + 1] = cosf(ang);
}

// ---------------- SGEMM: C[M,N] = A[M,K] @ B[K,N] + bias[N] ----------------
// 128x64 tile, BK=16, 256 threads, 8x4 per thread (split rows), double buffered.
__global__ __launch_bounds__(256) void sgemm_bias(
    const float* __restrict__ A, const float* __restrict__ B,
    const float* __restrict__ bias, float* __restrict__ C,
    int M, int Nn, int K)
{
    __shared__ float As[2][16][128];
    __shared__ float Bs[2][16][64];

    const int t  = threadIdx.x;
    const int m0 = blockIdx.y * 128;
    const int n0 = blockIdx.x * 64;
    const int tx = t & 15;         // cols: tx*4
    const int ty = t >> 4;         // rows: ty*4+r and 64+ty*4+r

    const int arow = t >> 1;            // 0..127
    const int ak   = (t & 1) * 8;       // 0 or 8
    const int vrow = t >> 4;            // 0..15 (B row)
    const int vcol = (t & 15) * 4;      // 0..60

    const int nk = K / 16;
    const bool aok = (m0 + arow) < M;

    const float* Aptr = A + (size_t)(m0 + arow) * K + ak;
    const float* Bptr = B + (size_t)vrow * Nn + n0 + vcol;

    float4 ra0 = make_float4(0,0,0,0), ra1 = ra0, rb0;
    if (aok) { ra0 = *(const float4*)Aptr; ra1 = *(const float4*)(Aptr + 4); }
    rb0 = *(const float4*)Bptr;
    {
        float va[8] = {ra0.x,ra0.y,ra0.z,ra0.w,ra1.x,ra1.y,ra1.z,ra1.w};
        #pragma unroll
        for (int j = 0; j < 8; j++) As[0][ak + j][arow] = va[j];
        *(float4*)&Bs[0][vrow][vcol] = rb0;
    }
    __syncthreads();

    float acc[8][4] = {};
    for (int kt = 0; kt < nk; kt++) {
        const int cur = kt & 1;
        if (kt + 1 < nk) {
            const float* Ap = Aptr + (kt + 1) * 16;
            const float* Bp = Bptr + (size_t)(kt + 1) * 16 * Nn;
            if (aok) { ra0 = *(const float4*)Ap; ra1 = *(const float4*)(Ap + 4); }
            rb0 = *(const float4*)Bp;
        }
        #pragma unroll
        for (int kk = 0; kk < 16; kk++) {
            float a[8], b[4];
            *(float4*)&a[0] = *(const float4*)&As[cur][kk][ty * 4];
            *(float4*)&a[4] = *(const float4*)&As[cur][kk][64 + ty * 4];
            *(float4*)&b[0] = *(const float4*)&Bs[cur][kk][tx * 4];
            #pragma unroll
            for (int r = 0; r < 8; r++)
                #pragma unroll
                for (int c = 0; c < 4; c++)
                    acc[r][c] = fmaf(a[r], b[c], acc[r][c]);
        }
        if (kt + 1 < nk) {
            const int nxt = cur ^ 1;
            float va[8] = {ra0.x,ra0.y,ra0.z,ra0.w,ra1.x,ra1.y,ra1.z,ra1.w};
            #pragma unroll
            for (int j = 0; j < 8; j++) As[nxt][ak + j][arow] = va[j];
            *(float4*)&Bs[nxt][vrow][vcol] = rb0;
        }
        __syncthreads();
    }

    float bv[4];
    #pragma unroll
    for (int c = 0; c < 4; c++) bv[c] = bias[n0 + tx * 4 + c];
    #pragma unroll
    for (int half = 0; half < 2; half++) {
        #pragma unroll
        for (int r = 0; r < 4; r++) {
            int m = m0 + half * 64 + ty * 4 + r;
            if (m < M) {
                int ar = half * 4 + r;
                float4 v = make_float4(acc[ar][0]+bv[0], acc[ar][1]+bv[1],
                                       acc[ar][2]+bv[2], acc[ar][3]+bv[3]);
                *(float4*)(C + (size_t)m * Nn + n0 + tx * 4) = v;
            }
        }
    }
}

// ---------------- fused scores: s = (q·(k+R) + rwb·k + rrb·R) / 8 ----------------
// 64x64 tile per block, 256 threads, 4x4 per thread. Dynamic smem.
__global__ __launch_bounds__(256) void scores_kernel(
    const float* __restrict__ rwb, const float* __restrict__ rrb)
{
    extern __shared__ float sm[];
    float* sq  = sm;                 // [64][65]
    float* sk  = sq + 64 * 65;       // [64][65]
    float* sR  = sk + 64 * 65;       // [127][65]
    float* skb = sR + 127 * 65;      // [64]
    float* srb = skb + 64;           // [127]

    const int k0 = blockIdx.x * 64;
    const int q0 = blockIdx.y * 64;
    const int nh = blockIdx.z;
    const int n  = nh / HH, h = nh % HH;
    const int t  = threadIdx.x;

    const float* qbase = g_q + (size_t)n * LL * EE + h * DD;
    const float* kbase = g_k + (size_t)n * LL * EE + h * DD;

    for (int i = t; i < 64 * 64; i += 256) {
        int r = i >> 6, c = i & 63;
        sq[r * 65 + c] = qbase[(size_t)(q0 + r) * EE + c];
        sk[r * 65 + c] = kbase[(size_t)(k0 + r) * EE + c];
    }
    const int rbase = q0 - k0 + 448;   // global R row for sR[0]
    for (int i = t; i < 127 * 64; i += 256) {
        int r = i >> 6, c = i & 63;
        sR[r * 65 + c] = g_R[(size_t)(rbase + r) * EE + h * DD + c];
    }
    __syncthreads();

    if (t < 64) {
        float s = 0.f;
        #pragma unroll
        for (int d = 0; d < DD; d++) s = fmaf(rwb[h * DD + d], sk[t * 65 + d], s);
        skb[t] = s;
    } else if (t < 191) {
        int r = t - 64;
        float s = 0.f;
        #pragma unroll
        for (int d = 0; d < DD; d++) s = fmaf(rrb[h * DD + d], sR[r * 65 + d], s);
        srb[r] = s;
    }
    __syncthreads();

    const int tx = t & 15;            // k-tile quarter
    const int ty = t >> 4;            // q-tile quarter
    const int qb = ty * 4, kbx = tx * 4;
    const int dbase = qb - kbx + 60;  // sR row for (r-c) = -3

    float acc[4][4] = {};
    #pragma unroll 4
    for (int d = 0; d < DD; d++) {
        float a[4], b[4], rr[7];
        #pragma unroll
        for (int r = 0; r < 4; r++) a[r] = sq[(qb + r) * 65 + d];
        #pragma unroll
        for (int c = 0; c < 4; c++) b[c] = sk[(kbx + c) * 65 + d];
        #pragma unroll
        for (int j = 0; j < 7; j++) rr[j] = sR[(dbase + j) * 65 + d];
        #pragma unroll
        for (int r = 0; r < 4; r++)
            #pragma unroll
            for (int c = 0; c < 4; c++)
                acc[r][c] = fmaf(a[r], b[c] + rr[3 + r - c], acc[r][c]);
    }

    const float scale = 0.125f;
    #pragma unroll
    for (int r = 0; r < 4; r++) {
        int qy = qb + r;
        float4 v;
        v.x = (acc[r][0] + skb[kbx+0] + srb[qy - (kbx+0) + 63]) * scale;
        v.y = (acc[r][1] + skb[kbx+1] + srb[qy - (kbx+1) + 63]) * scale;
        v.z = (acc[r][2] + skb[kbx+2] + srb[qy - (kbx+2) + 63]) * scale;
        v.w = (acc[r][3] + skb[kbx+3] + srb[qy - (kbx+3) + 63]) * scale;
        *(float4*)(g_s + (((size_t)nh) * LL + q0 + qy) * LL + k0 + kbx) = v;
    }
}

// ---------------- softmax over k ----------------
__global__ void softmax_kernel() {
    int row  = blockIdx.x * 8 + (threadIdx.x >> 5);
    int lane = threadIdx.x & 31;
    float* p = g_s + (size_t)row * LL;
    float vals[16];
    float mx = -INFINITY;
    #pragma unroll
    for (int i = 0; i < 16; i++) { vals[i] = p[lane + i * 32]; mx = fmaxf(mx, vals[i]); }
    #pragma unroll
    for (int o = 16; o; o >>= 1) mx = fmaxf(mx, __shfl_xor_sync(0xffffffffu, mx, o));
    float sum = 0.f;
    #pragma unroll
    for (int i = 0; i < 16; i++) { vals[i] = __expf(vals[i] - mx); sum += vals[i]; }
    #pragma unroll
    for (int o = 16; o; o >>= 1) sum += __shfl_xor_sync(0xffffffffu, sum, o);
    float inv = 1.f / sum;
    #pragma unroll
    for (int i = 0; i < 16; i++) p[lane + i * 32] = vals[i] * inv;
}

// ---------------- attn @ v : 128x64 tile, 8x4 per thread, double buffered ----------------
__global__ __launch_bounds__(256) void av_kernel() {
    __shared__ float sA[2][16][128];
    __shared__ float sV[2][16][64];

    const int nh = blockIdx.y;
    const int n  = nh / HH, h = nh % HH;
    const int q0 = blockIdx.x * 128;
    const int t  = threadIdx.x;
    const int tx = t & 15, ty = t >> 4;

    const int arow = t >> 1;
    const int ak   = (t & 1) * 8;
    const int vrow = t >> 4;
    const int vcol = (t & 15) * 4;

    const float* Aptr = g_s + ((size_t)nh * LL + q0 + arow) * LL + ak;
    const float* Vptr = g_v + ((size_t)n * LL + vrow) * EE + h * DD + vcol;

    float4 ra0, ra1, rb0;
    ra0 = *(const float4*)Aptr; ra1 = *(const float4*)(Aptr + 4);
    rb0 = *(const float4*)Vptr;
    {
        float va[8] = {ra0.x,ra0.y,ra0.z,ra0.w,ra1.x,ra1.y,ra1.z,ra1.w};
        #pragma unroll
        for (int j = 0; j < 8; j++) sA[0][ak + j][arow] = va[j];
        *(float4*)&sV[0][vrow][vcol] = rb0;
    }
    __syncthreads();

    float acc[8][4] = {};
    const int nk = LL / 16;   // 32
    for (int kt = 0; kt < nk; kt++) {
        const int cur = kt & 1;
        if (kt + 1 < nk) {
            const float* Ap = Aptr + (kt + 1) * 16;
            const float* Vp = Vptr + (size_t)(kt + 1) * 16 * EE;
            ra0 = *(const float4*)Ap; ra1 = *(const float4*)(Ap + 4);
            rb0 = *(const float4*)Vp;
        }
        #pragma unroll
        for (int kk = 0; kk < 16; kk++) {
            float a[8], b[4];
            *(float4*)&a[0] = *(const float4*)&sA[cur][kk][ty * 4];
            *(float4*)&a[4] = *(const float4*)&sA[cur][kk][64 + ty * 4];
            *(float4*)&b[0] = *(const float4*)&sV[cur][kk][tx * 4];
            #pragma unroll
            for (int r = 0; r < 8; r++)
                #pragma unroll
                for (int c = 0; c < 4; c++)
                    acc[r][c] = fmaf(a[r], b[c], acc[r][c]);
        }
        if (kt + 1 < nk) {
            const int nxt = cur ^ 1;
            float va[8] = {ra0.x,ra0.y,ra0.z,ra0.w,ra1.x,ra1.y,ra1.z,ra1.w};
            #pragma unroll
            for (int j = 0; j < 8; j++) sA[nxt][ak + j][arow] = va[j];
            *(float4*)&sV[nxt][vrow][vcol] = rb0;
        }
        __syncthreads();
    }

    #pragma unroll
    for (int half = 0; half < 2; half++) {
        #pragma unroll
        for (int r = 0; r < 4; r++) {
            int row = q0 + half * 64 + ty * 4 + r;
            int ar  = half * 4 + r;
            float4 v = make_float4(acc[ar][0], acc[ar][1], acc[ar][2], acc[ar][3]);
            *(float4*)(g_o + ((size_t)n * LL + row) * EE + h * DD + tx * 4) = v;
        }
    }
}

// ---------------- launch ----------------
extern "C" void kernel_launch(void* const* d_in, const int* in_sizes, int n_in,
                              void* d_out, int out_size) {
    const float* values = (const float*)d_in[0];
    const float* keys   = (const float*)d_in[1];
    const float* query  = (const float*)d_in[2];
    const float* Wq = (const float*)d_in[3];
    const float* bq = (const float*)d_in[4];
    const float* Wk = (const float*)d_in[5];
    const float* bk = (const float*)d_in[6];
    const float* Wv = (const float*)d_in[7];
    const float* bv = (const float*)d_in[8];
    const float* Wo = (const float*)d_in[9];
    const float* bo = (const float*)d_in[10];
    const float* Wpos = (const float*)d_in[11];
    const float* bpos = (const float*)d_in[12];
    const float* rwb  = (const float*)d_in[13];
    const float* rrb  = (const float*)d_in[14];
    float* out = (float*)d_out;

    float* pe_ptr; cudaGetSymbolAddress((void**)&pe_ptr, g_pe);
    float* R_ptr;  cudaGetSymbolAddress((void**)&R_ptr,  g_R);
    float* q_ptr;  cudaGetSymbolAddress((void**)&q_ptr,  g_q);
    float* k_ptr;  cudaGetSymbolAddress((void**)&k_ptr,  g_k);
    float* v_ptr;  cudaGetSymbolAddress((void**)&v_ptr,  g_v);
    float* o_ptr;  cudaGetSymbolAddress((void**)&o_ptr,  g_o);

    const int M = NB * LL;  // 4096
    const int SCORES_SMEM = (64*65 + 64*65 + 127*65 + 64 + 127) * 4;  // 67064 B
    static bool attr_set = false;
    if (!attr_set) {
        cudaFuncSetAttribute(scores_kernel,
                             cudaFuncAttributeMaxDynamicSharedMemorySize, SCORES_SMEM);
        attr_set = true;
    }

    // 1. sinusoid table
    pe_kernel<<<(MPOS * (EE / 2) + 255) / 256, 256>>>();

    // 2. R = pe @ Wpos + bpos   (1023 x 768)
    sgemm_bias<<<dim3(EE / 64, (MPOS + 127) / 128), 256>>>(pe_ptr, Wpos, bpos, R_ptr, MPOS, EE, EE);

    // 3-5. projections (4096 x 768)
    sgemm_bias<<<dim3(EE / 64, M / 128), 256>>>(query,  Wq, bq, q_ptr, M, EE, EE);
    sgemm_bias<<<dim3(EE / 64, M / 128), 256>>>(keys,   Wk, bk, k_ptr, M, EE, EE);
    sgemm_bias<<<dim3(EE / 64, M / 128), 256>>>(values, Wv, bv, v_ptr, M, EE, EE);

    // 6. fused relative-position scores
    scores_kernel<<<dim3(LL / 64, LL / 64, NB * HH), 256, SCORES_SMEM>>>(rwb, rrb);

    // 7. softmax
    softmax_kernel<<<(NB * HH * LL) / 8, 256>>>();

    // 8. attn @ v
    av_kernel<<<dim3(LL / 128, NB * HH), 256>>>();

    // 9. output projection -> d_out
    sgemm_bias<<<dim3(EE / 64, M / 128), 256>>>(o_ptr, Wo, bo, out, M, EE, EE);
}

// round 4
// speedup vs baseline: 2.3773x; 1.3759x over previous
#include <cuda_runtime.h>
#include <cuda_bf16.h>
#include <math.h>
#include <stdint.h>

#define NB 8
#define LL 512
#define EE 768
#define HH 12
#define DD 64
#define MPOS 1023   // 2*512-1

// ================= scratch =================
__device__ float g_R [MPOS * EE];
__device__ float g_q [NB * LL * EE];
__device__ float g_k [NB * LL * EE];
__device__ float g_v [NB * LL * EE];
__device__ float g_s [(size_t)NB * HH * LL * LL];
__device__ float g_o [NB * LL * EE];
__device__ __nv_bfloat16 g_Ah[NB * LL * EE];   // reused: pe / query / keys / values / o
__device__ __nv_bfloat16 g_Al[NB * LL * EE];
__device__ __nv_bfloat16 g_Bh[EE * EE];        // transposed-split weights
__device__ __nv_bfloat16 g_Bl[EE * EE];

// ================= helpers =================
__device__ __forceinline__ uint32_t smem_to_u32(const void* p) {
    uint32_t a;
    asm("{ .reg .u64 tmp; cvta.to.shared.u64 tmp, %1; cvt.u32.u64 %0, tmp; }" : "=r"(a) : "l"(p));
    return a;
}
__device__ __forceinline__ void cp16(uint32_t dst, const void* src, uint32_t sz) {
    asm volatile("cp.async.cg.shared.global [%0], [%1], 16, %2;"
                 :: "r"(dst), "l"(src), "r"(sz) : "memory");
}
__device__ __forceinline__ void mma16816(float* c, const uint32_t* a, const uint32_t* b) {
    asm volatile("mma.sync.aligned.m16n8k16.row.col.f32.bf16.bf16.f32 "
        "{%0,%1,%2,%3}, {%4,%5,%6,%7}, {%8,%9}, {%0,%1,%2,%3};"
        : "+f"(c[0]), "+f"(c[1]), "+f"(c[2]), "+f"(c[3])
        : "r"(a[0]), "r"(a[1]), "r"(a[2]), "r"(a[3]), "r"(b[0]), "r"(b[1]));
}

// ================= sinusoid table (split bf16 directly) =================
__global__ void pe_kernel(__nv_bfloat16* __restrict__ hi, __nv_bfloat16* __restrict__ lo) {
    int i = blockIdx.x * blockDim.x + threadIdx.x;
    if (i >= MPOS * (EE / 2)) return;
    int p = i / (EE / 2);
    int m = i % (EE / 2);
    float div = expf((float)(2 * m) * (-9.210340371976184f / (float)EE));
    float ang = (float)p * div;
    float s = sinf(ang), c = cosf(ang);
    __nv_bfloat16 sh = __float2bfloat16(s);
    __nv_bfloat16 ch = __float2bfloat16(c);
    hi[(size_t)p * EE + 2 * m]     = sh;
    hi[(size_t)p * EE + 2 * m + 1] = ch;
    lo[(size_t)p * EE + 2 * m]     = __float2bfloat16(s - __bfloat162float(sh));
    lo[(size_t)p * EE + 2 * m + 1] = __float2bfloat16(c - __bfloat162float(ch));
}

// ================= fp32 -> bf16 hi/lo split =================
__global__ void split_kernel(const float* __restrict__ src,
                             __nv_bfloat16* __restrict__ hi, __nv_bfloat16* __restrict__ lo, int n) {
    int i = (blockIdx.x * blockDim.x + threadIdx.x) * 4;
    if (i >= n) return;
    float4 v = *(const float4*)(src + i);
    float vv[4] = {v.x, v.y, v.z, v.w};
    #pragma unroll
    for (int j = 0; j < 4; j++) {
        __nv_bfloat16 h = __float2bfloat16(vv[j]);
        hi[i + j] = h;
        lo[i + j] = __float2bfloat16(vv[j] - __bfloat162float(h));
    }
}

// ================= W [K,N] -> Wt [N,K] bf16 hi/lo =================
__global__ void tsplit_kernel(const float* __restrict__ W,
                              __nv_bfloat16* __restrict__ Th, __nv_bfloat16* __restrict__ Tl) {
    __shared__ float tile[32][33];
    int bx = blockIdx.x * 32;
    int by = blockIdx.y * 32;
    int x = threadIdx.x, y0 = threadIdx.y;
    #pragma unroll
    for (int j = 0; j < 32; j += 8)
        tile[y0 + j][x] = W[(size_t)(by + y0 + j) * EE + bx + x];
    __syncthreads();
    #pragma unroll
    for (int j = 0; j < 32; j += 8) {
        int n = bx + y0 + j, k = by + x;
        float v = tile[x][y0 + j];
        __nv_bfloat16 h = __float2bfloat16(v);
        Th[(size_t)n * EE + k] = h;
        Tl[(size_t)n * EE + k] = __float2bfloat16(v - __bfloat162float(h));
    }
}

// ================= mma.sync split-bf16 GEMM =================
// C[M,Nn] = (Ah+Al)[M,K] @ (Bh+Bl)^T[Nn,K] + bias.  CTA tile 128x128, 8 warps,
// warp tile 32x64, K-chunk 32, 2-stage cp.async pipeline.
// SMEM halves layout per stage (stride 20480): AH@0, AL@5120, BH@10240, BL@15360,
// padded row stride 40 halves (conflict-free fragment LDS, 16B-aligned cp.async).
#define GSMEM (2 * 20480 * 2)

__global__ __launch_bounds__(256) void gemm_mma(
    const __nv_bfloat16* __restrict__ Ah, const __nv_bfloat16* __restrict__ Al,
    const __nv_bfloat16* __restrict__ Bh, const __nv_bfloat16* __restrict__ Bl,
    const float* __restrict__ bias, float* __restrict__ C, int M, int Nn, int K)
{
    extern __shared__ __nv_bfloat16 sm[];
    const uint32_t sbase = smem_to_u32(sm);
    const int t = threadIdx.x;
    const int lane = t & 31, wid = t >> 5;
    const int wm = wid & 3, wn = wid >> 2;       // warp tile (wm*32, wn*64)
    const int m0 = blockIdx.y * 128, n0c = blockIdx.x * 128;
    const int g = lane >> 2, tc = lane & 3;

    const int arow = t >> 1, aq = t & 1;         // loader mapping (A and B rows 0..127)
    const uint32_t asz = (m0 + arow < M) ? 16u : 0u;
    const int nk = K / 32;

    float acc[2][8][4];
    #pragma unroll
    for (int a = 0; a < 2; a++)
        #pragma unroll
        for (int b = 0; b < 8; b++)
            #pragma unroll
            for (int cix = 0; cix < 4; cix++) acc[a][b][cix] = 0.f;

    // ---- issue stage copies ----
    auto issue = [&](int c) {
        const int st = c & 1;
        const int k0 = c * 32;
        const uint32_t soff = (uint32_t)st * 20480;
        const __nv_bfloat16* gah = Ah + (size_t)(m0 + arow) * K + k0 + aq * 16;
        const __nv_bfloat16* gal = Al + (size_t)(m0 + arow) * K + k0 + aq * 16;
        const __nv_bfloat16* gbh = Bh + (size_t)(n0c + arow) * K + k0 + aq * 16;
        const __nv_bfloat16* gbl = Bl + (size_t)(n0c + arow) * K + k0 + aq * 16;
        uint32_t da  = sbase + (soff + arow * 40 + aq * 16) * 2;
        cp16(da,              gah,     asz);
        cp16(da + 16,         gah + 8, asz);
        cp16(da + 5120 * 2,       gal,     asz);
        cp16(da + 5120 * 2 + 16,  gal + 8, asz);
        cp16(da + 10240 * 2,      gbh,     16u);
        cp16(da + 10240 * 2 + 16, gbh + 8, 16u);
        cp16(da + 15360 * 2,      gbl,     16u);
        cp16(da + 15360 * 2 + 16, gbl + 8, 16u);
    };

    issue(0);
    asm volatile("cp.async.commit_group;");

    for (int c = 0; c < nk; c++) {
        if (c + 1 < nk) {
            issue(c + 1);
            asm volatile("cp.async.commit_group;");
            asm volatile("cp.async.wait_group 1;");
        } else {
            asm volatile("cp.async.wait_group 0;");
        }
        __syncthreads();

        const uint32_t s0 = (uint32_t)(c & 1) * 20480;
        #pragma unroll
        for (int ks = 0; ks < 2; ks++) {
            const int kk = ks * 16 + tc * 2;
            uint32_t fah[2][4], fal[2][4];
            #pragma unroll
            for (int mt = 0; mt < 2; mt++) {
                int r = wm * 32 + mt * 16 + g;
                fah[mt][0] = *(const uint32_t*)&sm[s0 + r * 40 + kk];
                fah[mt][1] = *(const uint32_t*)&sm[s0 + (r + 8) * 40 + kk];
                fah[mt][2] = *(const uint32_t*)&sm[s0 + r * 40 + kk + 8];
                fah[mt][3] = *(const uint32_t*)&sm[s0 + (r + 8) * 40 + kk + 8];
                fal[mt][0] = *(const uint32_t*)&sm[s0 + 5120 + r * 40 + kk];
                fal[mt][1] = *(const uint32_t*)&sm[s0 + 5120 + (r + 8) * 40 + kk];
                fal[mt][2] = *(const uint32_t*)&sm[s0 + 5120 + r * 40 + kk + 8];
                fal[mt][3] = *(const uint32_t*)&sm[s0 + 5120 + (r + 8) * 40 + kk + 8];
            }
            #pragma unroll
            for (int nt = 0; nt < 8; nt++) {
                int n = wn * 64 + nt * 8 + g;
                uint32_t fbh[2], fbl[2];
                fbh[0] = *(const uint32_t*)&sm[s0 + 10240 + n * 40 + kk];
                fbh[1] = *(const uint32_t*)&sm[s0 + 10240 + n * 40 + kk + 8];
                fbl[0] = *(const uint32_t*)&sm[s0 + 15360 + n * 40 + kk];
                fbl[1] = *(const uint32_t*)&sm[s0 + 15360 + n * 40 + kk + 8];
                #pragma unroll
                for (int mt = 0; mt < 2; mt++) {
                    mma16816(acc[mt][nt], fah[mt], fbh);
                    mma16816(acc[mt][nt], fah[mt], fbl);
                    mma16816(acc[mt][nt], fal[mt], fbh);
                }
            }
        }
        __syncthreads();
    }

    // ---- epilogue ----
    #pragma unroll
    for (int mt = 0; mt < 2; mt++) {
        int r = m0 + wm * 32 + mt * 16 + g;
        #pragma unroll
        for (int nt = 0; nt < 8; nt++) {
            int cc = n0c + wn * 64 + nt * 8 + tc * 2;
            float b0 = bias[cc], b1 = bias[cc + 1];
            if (r < M) {
                float2 v = make_float2(acc[mt][nt][0] + b0, acc[mt][nt][1] + b1);
                *(float2*)&C[(size_t)r * Nn + cc] = v;
            }
            if (r + 8 < M) {
                float2 v = make_float2(acc[mt][nt][2] + b0, acc[mt][nt][3] + b1);
                *(float2*)&C[(size_t)(r + 8) * Nn + cc] = v;
            }
        }
    }
}

// ================= fused scores (fp32 SIMT) =================
__global__ __launch_bounds__(256) void scores_kernel(
    const float* __restrict__ rwb, const float* __restrict__ rrb)
{
    extern __shared__ float smf[];
    float* sq  = smf;
    float* sk  = sq + 64 * 65;
    float* sR  = sk + 64 * 65;
    float* skb = sR + 127 * 65;
    float* srb = skb + 64;

    const int k0 = blockIdx.x * 64;
    const int q0 = blockIdx.y * 64;
    const int nh = blockIdx.z;
    const int n  = nh / HH, h = nh % HH;
    const int t  = threadIdx.x;

    const float* qbase = g_q + (size_t)n * LL * EE + h * DD;
    const float* kbase = g_k + (size_t)n * LL * EE + h * DD;

    for (int i = t; i < 64 * 64; i += 256) {
        int r = i >> 6, c = i & 63;
        sq[r * 65 + c] = qbase[(size_t)(q0 + r) * EE + c];
        sk[r * 65 + c] = kbase[(size_t)(k0 + r) * EE + c];
    }
    const int rbase = q0 - k0 + 448;
    for (int i = t; i < 127 * 64; i += 256) {
        int r = i >> 6, c = i & 63;
        sR[r * 65 + c] = g_R[(size_t)(rbase + r) * EE + h * DD + c];
    }
    __syncthreads();

    if (t < 64) {
        float s = 0.f;
        #pragma unroll
        for (int d = 0; d < DD; d++) s = fmaf(rwb[h * DD + d], sk[t * 65 + d], s);
        skb[t] = s;
    } else if (t < 191) {
        int r = t - 64;
        float s = 0.f;
        #pragma unroll
        for (int d = 0; d < DD; d++) s = fmaf(rrb[h * DD + d], sR[r * 65 + d], s);
        srb[r] = s;
    }
    __syncthreads();

    const int tx = t & 15;
    const int ty = t >> 4;
    const int qb = ty * 4, kbx = tx * 4;
    const int dbase = qb - kbx + 60;

    float acc[4][4] = {};
    #pragma unroll 4
    for (int d = 0; d < DD; d++) {
        float a[4], b[4], rr[7];
        #pragma unroll
        for (int r = 0; r < 4; r++) a[r] = sq[(qb + r) * 65 + d];
        #pragma unroll
        for (int c = 0; c < 4; c++) b[c] = sk[(kbx + c) * 65 + d];
        #pragma unroll
        for (int j = 0; j < 7; j++) rr[j] = sR[(dbase + j) * 65 + d];
        #pragma unroll
        for (int r = 0; r < 4; r++)
            #pragma unroll
            for (int c = 0; c < 4; c++)
                acc[r][c] = fmaf(a[r], b[c] + rr[3 + r - c], acc[r][c]);
    }

    const float scale = 0.125f;
    #pragma unroll
    for (int r = 0; r < 4; r++) {
        int qy = qb + r;
        float4 v;
        v.x = (acc[r][0] + skb[kbx+0] + srb[qy - (kbx+0) + 63]) * scale;
        v.y = (acc[r][1] + skb[kbx+1] + srb[qy - (kbx+1) + 63]) * scale;
        v.z = (acc[r][2] + skb[kbx+2] + srb[qy - (kbx+2) + 63]) * scale;
        v.w = (acc[r][3] + skb[kbx+3] + srb[qy - (kbx+3) + 63]) * scale;
        *(float4*)(g_s + (((size_t)nh) * LL + q0 + qy) * LL + k0 + kbx) = v;
    }
}

// ================= softmax =================
__global__ void softmax_kernel() {
    int row  = blockIdx.x * 8 + (threadIdx.x >> 5);
    int lane = threadIdx.x & 31;
    float* p = g_s + (size_t)row * LL;
    float vals[16];
    float mx = -INFINITY;
    #pragma unroll
    for (int i = 0; i < 16; i++) { vals[i] = p[lane + i * 32]; mx = fmaxf(mx, vals[i]); }
    #pragma unroll
    for (int o = 16; o; o >>= 1) mx = fmaxf(mx, __shfl_xor_sync(0xffffffffu, mx, o));
    float sum = 0.f;
    #pragma unroll
    for (int i = 0; i < 16; i++) { vals[i] = __expf(vals[i] - mx); sum += vals[i]; }
    #pragma unroll
    for (int o = 16; o; o >>= 1) sum += __shfl_xor_sync(0xffffffffu, sum, o);
    float inv = 1.f / sum;
    #pragma unroll
    for (int i = 0; i < 16; i++) p[lane + i * 32] = vals[i] * inv;
}

// ================= attn @ v (fp32 SIMT) =================
__global__ __launch_bounds__(256) void av_kernel() {
    __shared__ float sA[2][16][128];
    __shared__ float sV[2][16][64];

    const int nh = blockIdx.y;
    const int n  = nh / HH, h = nh % HH;
    const int q0 = blockIdx.x * 128;
    const int t  = threadIdx.x;
    const int tx = t & 15, ty = t >> 4;

    const int arow = t >> 1;
    const int ak   = (t & 1) * 8;
    const int vrow = t >> 4;
    const int vcol = (t & 15) * 4;

    const float* Aptr = g_s + ((size_t)nh * LL + q0 + arow) * LL + ak;
    const float* Vptr = g_v + ((size_t)n * LL + vrow) * EE + h * DD + vcol;

    float4 ra0, ra1, rb0;
    ra0 = *(const float4*)Aptr; ra1 = *(const float4*)(Aptr + 4);
    rb0 = *(const float4*)Vptr;
    {
        float va[8] = {ra0.x,ra0.y,ra0.z,ra0.w,ra1.x,ra1.y,ra1.z,ra1.w};
        #pragma unroll
        for (int j = 0; j < 8; j++) sA[0][ak + j][arow] = va[j];
        *(float4*)&sV[0][vrow][vcol] = rb0;
    }
    __syncthreads();

    float acc[8][4] = {};
    const int nk = LL / 16;
    for (int kt = 0; kt < nk; kt++) {
        const int cur = kt & 1;
        if (kt + 1 < nk) {
            const float* Ap = Aptr + (kt + 1) * 16;
            const float* Vp = Vptr + (size_t)(kt + 1) * 16 * EE;
            ra0 = *(const float4*)Ap; ra1 = *(const float4*)(Ap + 4);
            rb0 = *(const float4*)Vp;
        }
        #pragma unroll
        for (int kk = 0; kk < 16; kk++) {
            float a[8], b[4];
            *(float4*)&a[0] = *(const float4*)&sA[cur][kk][ty * 4];
            *(float4*)&a[4] = *(const float4*)&sA[cur][kk][64 + ty * 4];
            *(float4*)&b[0] = *(const float4*)&sV[cur][kk][tx * 4];
            #pragma unroll
            for (int r = 0; r < 8; r++)
                #pragma unroll
                for (int c = 0; c < 4; c++)
                    acc[r][c] = fmaf(a[r], b[c], acc[r][c]);
        }
        if (kt + 1 < nk) {
            const int nxt = cur ^ 1;
            float va[8] = {ra0.x,ra0.y,ra0.z,ra0.w,ra1.x,ra1.y,ra1.z,ra1.w};
            #pragma unroll
            for (int j = 0; j < 8; j++) sA[nxt][ak + j][arow] = va[j];
            *(float4*)&sV[nxt][vrow][vcol] = rb0;
        }
        __syncthreads();
    }

    #pragma unroll
    for (int half = 0; half < 2; half++) {
        #pragma unroll
        for (int r = 0; r < 4; r++) {
            int row = q0 + half * 64 + ty * 4 + r;
            int ar  = half * 4 + r;
            float4 v = make_float4(acc[ar][0], acc[ar][1], acc[ar][2], acc[ar][3]);
            *(float4*)(g_o + ((size_t)n * LL + row) * EE + h * DD + tx * 4) = v;
        }
    }
}

// ================= launch =================
extern "C" void kernel_launch(void* const* d_in, const int* in_sizes, int n_in,
                              void* d_out, int out_size) {
    const float* values = (const float*)d_in[0];
    const float* keys   = (const float*)d_in[1];
    const float* query  = (const float*)d_in[2];
    const float* Wq = (const float*)d_in[3];
    const float* bq = (const float*)d_in[4];
    const float* Wk = (const float*)d_in[5];
    const float* bk = (const float*)d_in[6];
    const float* Wv = (const float*)d_in[7];
    const float* bv = (const float*)d_in[8];
    const float* Wo = (const float*)d_in[9];
    const float* bo = (const float*)d_in[10];
    const float* Wpos = (const float*)d_in[11];
    const float* bpos = (const float*)d_in[12];
    const float* rwb  = (const float*)d_in[13];
    const float* rrb  = (const float*)d_in[14];
    float* out = (float*)d_out;

    float* R_ptr;  cudaGetSymbolAddress((void**)&R_ptr,  g_R);
    float* q_ptr;  cudaGetSymbolAddress((void**)&q_ptr,  g_q);
    float* k_ptr;  cudaGetSymbolAddress((void**)&k_ptr,  g_k);
    float* v_ptr;  cudaGetSymbolAddress((void**)&v_ptr,  g_v);
    float* o_ptr;  cudaGetSymbolAddress((void**)&o_ptr,  g_o);
    __nv_bfloat16* Ah; cudaGetSymbolAddress((void**)&Ah, g_Ah);
    __nv_bfloat16* Al; cudaGetSymbolAddress((void**)&Al, g_Al);
    __nv_bfloat16* Bh; cudaGetSymbolAddress((void**)&Bh, g_Bh);
    __nv_bfloat16* Bl; cudaGetSymbolAddress((void**)&Bl, g_Bl);

    const int M = NB * LL;  // 4096
    const int SCORES_SMEM = (64*65 + 64*65 + 127*65 + 64 + 127) * 4;
    static bool attr_set = false;
    if (!attr_set) {
        cudaFuncSetAttribute(scores_kernel, cudaFuncAttributeMaxDynamicSharedMemorySize, SCORES_SMEM);
        cudaFuncSetAttribute(gemm_mma, cudaFuncAttributeMaxDynamicSharedMemorySize, GSMEM);
        attr_set = true;
    }

    const dim3 tsg(24, 24), tsb(32, 8);
    const int splitN = M * EE;
    const int splitB = (splitN / 4 + 255) / 256;

    // R = pe @ Wpos + bpos   (1023 x 768)
    pe_kernel<<<(MPOS * (EE / 2) + 255) / 256, 256>>>(Ah, Al);
    tsplit_kernel<<<tsg, tsb>>>(Wpos, Bh, Bl);
    gemm_mma<<<dim3(EE / 128, 8), 256, GSMEM>>>(Ah, Al, Bh, Bl, bpos, R_ptr, MPOS, EE, EE);

    // q/k/v projections
    split_kernel<<<splitB, 256>>>(query, Ah, Al, splitN);
    tsplit_kernel<<<tsg, tsb>>>(Wq, Bh, Bl);
    gemm_mma<<<dim3(EE / 128, M / 128), 256, GSMEM>>>(Ah, Al, Bh, Bl, bq, q_ptr, M, EE, EE);

    split_kernel<<<splitB, 256>>>(keys, Ah, Al, splitN);
    tsplit_kernel<<<tsg, tsb>>>(Wk, Bh, Bl);
    gemm_mma<<<dim3(EE / 128, M / 128), 256, GSMEM>>>(Ah, Al, Bh, Bl, bk, k_ptr, M, EE, EE);

    split_kernel<<<splitB, 256>>>(values, Ah, Al, splitN);
    tsplit_kernel<<<tsg, tsb>>>(Wv, Bh, Bl);
    gemm_mma<<<dim3(EE / 128, M / 128), 256, GSMEM>>>(Ah, Al, Bh, Bl, bv, v_ptr, M, EE, EE);

    // attention (fp32)
    scores_kernel<<<dim3(LL / 64, LL / 64, NB * HH), 256, SCORES_SMEM>>>(rwb, rrb);
    softmax_kernel<<<(NB * HH * LL) / 8, 256>>>();
    av_kernel<<<dim3(LL / 128, NB * HH), 256>>>();

    // output projection
    split_kernel<<<splitB, 256>>>(o_ptr, Ah, Al, splitN);
    tsplit_kernel<<<tsg, tsb>>>(Wo, Bh, Bl);
    gemm_mma<<<dim3(EE / 128, M / 128), 256, GSMEM>>>(Ah, Al, Bh, Bl, bo, out, M, EE, EE);
}

// round 5
// speedup vs baseline: 3.0394x; 1.2785x over previous
#include <cuda_runtime.h>
#include <cuda_bf16.h>
#include <math.h>
#include <stdint.h>

#define NB 8
#define LL 512
#define EE 768
#define HH 12
#define DD 64
#define MPOS 1023   // 2*512-1
#define NHB (NB * HH)   // 96

// ================= scratch =================
__device__ float g_R [MPOS * EE];
__device__ float g_q [NB * LL * EE];
__device__ float g_k [NB * LL * EE];
__device__ float g_v [NB * LL * EE];
__device__ float g_s [(size_t)NHB * LL * LL];          // ac scores
__device__ float g_bd[(size_t)NHB * LL * 1024];        // bd_full
__device__ float g_o [NB * LL * EE];
__device__ __nv_bfloat16 g_Ah[NB * LL * EE];   // split staging (inputs / o)
__device__ __nv_bfloat16 g_Al[NB * LL * EE];
__device__ __nv_bfloat16 g_Bh[EE * EE];        // transposed-split weights
__device__ __nv_bfloat16 g_Bl[EE * EE];
// per-head re-layouts [nh][l][d]
__device__ __nv_bfloat16 g_qwh[NHB * LL * DD], g_qwl[NHB * LL * DD];
__device__ __nv_bfloat16 g_qrh[NHB * LL * DD], g_qrl[NHB * LL * DD];
__device__ __nv_bfloat16 g_khh[NHB * LL * DD], g_khl[NHB * LL * DD];
__device__ __nv_bfloat16 g_vth[NHB * DD * LL], g_vtl[NHB * DD * LL];   // [nh][d][l]
__device__ __nv_bfloat16 g_Rth[HH * 1024 * DD], g_Rtl[HH * 1024 * DD]; // [h][j][d], j padded
__device__ __nv_bfloat16 g_ath[(size_t)NHB * LL * LL], g_atl[(size_t)NHB * LL * LL]; // attn hi/lo

// ================= helpers =================
__device__ __forceinline__ uint32_t smem_to_u32(const void* p) {
    uint32_t a;
    asm("{ .reg .u64 tmp; cvta.to.shared.u64 tmp, %1; cvt.u32.u64 %0, tmp; }" : "=r"(a) : "l"(p));
    return a;
}
__device__ __forceinline__ void cp16(uint32_t dst, const void* src, uint32_t sz) {
    asm volatile("cp.async.cg.shared.global [%0], [%1], 16, %2;"
                 :: "r"(dst), "l"(src), "r"(sz) : "memory");
}
__device__ __forceinline__ void mma16816(float* c, const uint32_t* a, const uint32_t* b) {
    asm volatile("mma.sync.aligned.m16n8k16.row.col.f32.bf16.bf16.f32 "
        "{%0,%1,%2,%3}, {%4,%5,%6,%7}, {%8,%9}, {%0,%1,%2,%3};"
        : "+f"(c[0]), "+f"(c[1]), "+f"(c[2]), "+f"(c[3])
        : "r"(a[0]), "r"(a[1]), "r"(a[2]), "r"(a[3]), "r"(b[0]), "r"(b[1]));
}
__device__ __forceinline__ void bsplit(float v, __nv_bfloat16* hi, __nv_bfloat16* lo) {
    __nv_bfloat16 h = __float2bfloat16(v);
    *hi = h;
    *lo = __float2bfloat16(v - __bfloat162float(h));
}

// ================= sinusoid table (split bf16 directly) =================
__global__ void pe_kernel(__nv_bfloat16* __restrict__ hi, __nv_bfloat16* __restrict__ lo) {
    int i = blockIdx.x * blockDim.x + threadIdx.x;
    if (i >= MPOS * (EE / 2)) return;
    int p = i / (EE / 2);
    int m = i % (EE / 2);
    float div = expf((float)(2 * m) * (-9.210340371976184f / (float)EE));
    float ang = (float)p * div;
    bsplit(sinf(ang), &hi[(size_t)p * EE + 2 * m],     &lo[(size_t)p * EE + 2 * m]);
    bsplit(cosf(ang), &hi[(size_t)p * EE + 2 * m + 1], &lo[(size_t)p * EE + 2 * m + 1]);
}

// ================= fp32 -> bf16 hi/lo split =================
__global__ void split_kernel(const float* __restrict__ src,
                             __nv_bfloat16* __restrict__ hi, __nv_bfloat16* __restrict__ lo, int n) {
    int i = (blockIdx.x * blockDim.x + threadIdx.x) * 4;
    if (i >= n) return;
    float4 v = *(const float4*)(src + i);
    float vv[4] = {v.x, v.y, v.z, v.w};
    #pragma unroll
    for (int j = 0; j < 4; j++) bsplit(vv[j], &hi[i + j], &lo[i + j]);
}

// ================= W [K,N] -> Wt [N,K] bf16 hi/lo =================
__global__ void tsplit_kernel(const float* __restrict__ W,
                              __nv_bfloat16* __restrict__ Th, __nv_bfloat16* __restrict__ Tl) {
    __shared__ float tile[32][33];
    int bx = blockIdx.x * 32;
    int by = blockIdx.y * 32;
    int x = threadIdx.x, y0 = threadIdx.y;
    #pragma unroll
    for (int j = 0; j < 32; j += 8)
        tile[y0 + j][x] = W[(size_t)(by + y0 + j) * EE + bx + x];
    __syncthreads();
    #pragma unroll
    for (int j = 0; j < 32; j += 8) {
        int n = bx + y0 + j, k = by + x;
        bsplit(tile[x][y0 + j], &Th[(size_t)n * EE + k], &Tl[(size_t)n * EE + k]);
    }
}

// ================= weight GEMM (mma.sync split-bf16), 128x128 tile =================
#define GSMEM (2 * 20480 * 2)
__global__ __launch_bounds__(256) void gemm_mma(
    const __nv_bfloat16* __restrict__ Ah, const __nv_bfloat16* __restrict__ Al,
    const __nv_bfloat16* __restrict__ Bh, const __nv_bfloat16* __restrict__ Bl,
    const float* __restrict__ bias, float* __restrict__ C, int M, int Nn, int K)
{
    extern __shared__ __nv_bfloat16 sm[];
    const uint32_t sbase = smem_to_u32(sm);
    const int t = threadIdx.x;
    const int lane = t & 31, wid = t >> 5;
    const int wm = wid & 3, wn = wid >> 2;
    const int m0 = blockIdx.y * 128, n0c = blockIdx.x * 128;
    const int g = lane >> 2, tc = lane & 3;

    const int arow = t >> 1, aq = t & 1;
    const uint32_t asz = (m0 + arow < M) ? 16u : 0u;
    const int nk = K / 32;

    float acc[2][8][4];
    #pragma unroll
    for (int a = 0; a < 2; a++)
        #pragma unroll
        for (int b = 0; b < 8; b++)
            #pragma unroll
            for (int cix = 0; cix < 4; cix++) acc[a][b][cix] = 0.f;

    auto issue = [&](int c) {
        const int st = c & 1;
        const int k0 = c * 32;
        const uint32_t soff = (uint32_t)st * 20480;
        const __nv_bfloat16* gah = Ah + (size_t)(m0 + arow) * K + k0 + aq * 16;
        const __nv_bfloat16* gal = Al + (size_t)(m0 + arow) * K + k0 + aq * 16;
        const __nv_bfloat16* gbh = Bh + (size_t)(n0c + arow) * K + k0 + aq * 16;
        const __nv_bfloat16* gbl = Bl + (size_t)(n0c + arow) * K + k0 + aq * 16;
        uint32_t da = sbase + (soff + arow * 40 + aq * 16) * 2;
        cp16(da,              gah,     asz);
        cp16(da + 16,         gah + 8, asz);
        cp16(da + 5120 * 2,       gal,     asz);
        cp16(da + 5120 * 2 + 16,  gal + 8, asz);
        cp16(da + 10240 * 2,      gbh,     16u);
        cp16(da + 10240 * 2 + 16, gbh + 8, 16u);
        cp16(da + 15360 * 2,      gbl,     16u);
        cp16(da + 15360 * 2 + 16, gbl + 8, 16u);
    };

    issue(0);
    asm volatile("cp.async.commit_group;");

    for (int c = 0; c < nk; c++) {
        if (c + 1 < nk) {
            issue(c + 1);
            asm volatile("cp.async.commit_group;");
            asm volatile("cp.async.wait_group 1;");
        } else {
            asm volatile("cp.async.wait_group 0;");
        }
        __syncthreads();
        const uint32_t s0 = (uint32_t)(c & 1) * 20480;
        #pragma unroll
        for (int ks = 0; ks < 2; ks++) {
            const int kk = ks * 16 + tc * 2;
            uint32_t fah[2][4], fal[2][4];
            #pragma unroll
            for (int mt = 0; mt < 2; mt++) {
                int r = wm * 32 + mt * 16 + g;
                fah[mt][0] = *(const uint32_t*)&sm[s0 + r * 40 + kk];
                fah[mt][1] = *(const uint32_t*)&sm[s0 + (r + 8) * 40 + kk];
                fah[mt][2] = *(const uint32_t*)&sm[s0 + r * 40 + kk + 8];
                fah[mt][3] = *(const uint32_t*)&sm[s0 + (r + 8) * 40 + kk + 8];
                fal[mt][0] = *(const uint32_t*)&sm[s0 + 5120 + r * 40 + kk];
                fal[mt][1] = *(const uint32_t*)&sm[s0 + 5120 + (r + 8) * 40 + kk];
                fal[mt][2] = *(const uint32_t*)&sm[s0 + 5120 + r * 40 + kk + 8];
                fal[mt][3] = *(const uint32_t*)&sm[s0 + 5120 + (r + 8) * 40 + kk + 8];
            }
            #pragma unroll
            for (int nt = 0; nt < 8; nt++) {
                int n = wn * 64 + nt * 8 + g;
                uint32_t fbh[2], fbl[2];
                fbh[0] = *(const uint32_t*)&sm[s0 + 10240 + n * 40 + kk];
                fbh[1] = *(const uint32_t*)&sm[s0 + 10240 + n * 40 + kk + 8];
                fbl[0] = *(const uint32_t*)&sm[s0 + 15360 + n * 40 + kk];
                fbl[1] = *(const uint32_t*)&sm[s0 + 15360 + n * 40 + kk + 8];
                #pragma unroll
                for (int mt = 0; mt < 2; mt++) {
                    mma16816(acc[mt][nt], fah[mt], fbh);
                    mma16816(acc[mt][nt], fah[mt], fbl);
                    mma16816(acc[mt][nt], fal[mt], fbh);
                }
            }
        }
        __syncthreads();
    }

    #pragma unroll
    for (int mt = 0; mt < 2; mt++) {
        int r = m0 + wm * 32 + mt * 16 + g;
        #pragma unroll
        for (int nt = 0; nt < 8; nt++) {
            int cc = n0c + wn * 64 + nt * 8 + tc * 2;
            float b0 = bias[cc], b1 = bias[cc + 1];
            if (r < M) {
                float2 v = make_float2(acc[mt][nt][0] + b0, acc[mt][nt][1] + b1);
                *(float2*)&C[(size_t)r * Nn + cc] = v;
            }
            if (r + 8 < M) {
                float2 v = make_float2(acc[mt][nt][2] + b0, acc[mt][nt][3] + b1);
                *(float2*)&C[(size_t)(r + 8) * Nn + cc] = v;
            }
        }
    }
}

// ================= batched MMA (K=64): ac and bd score GEMMs =================
// C[z][512, Nn] = A[z][512,64] @ B[bz][*,64]^T.  bmod=1 -> bd (B per head, diagonal tiles).
__global__ __launch_bounds__(256) void bmma(
    const __nv_bfloat16* __restrict__ Ah, const __nv_bfloat16* __restrict__ Al,
    const __nv_bfloat16* __restrict__ Bh, const __nv_bfloat16* __restrict__ Bl,
    float* __restrict__ C, int Nn, int bmod)
{
    extern __shared__ __nv_bfloat16 sm[];
    const uint32_t sbase = smem_to_u32(sm);
    const int t = threadIdx.x;
    const int lane = t & 31, wid = t >> 5;
    const int wm = wid & 3, wn = wid >> 2;
    const int z = blockIdx.z;
    const int m0 = blockIdx.y * 128;
    const int n0c = bmod ? (blockIdx.y + blockIdx.x) * 128 : blockIdx.x * 128;
    const int g = lane >> 2, tc = lane & 3;

    const __nv_bfloat16* Abh = Ah + (size_t)z * LL * DD;
    const __nv_bfloat16* Abl = Al + (size_t)z * LL * DD;
    const size_t bstr = bmod ? (size_t)(z % HH) * 1024 * DD : (size_t)z * LL * DD;
    const __nv_bfloat16* Bbh = Bh + bstr;
    const __nv_bfloat16* Bbl = Bl + bstr;

    const int arow = t >> 1, aq = t & 1;

    float acc[2][8][4];
    #pragma unroll
    for (int a = 0; a < 2; a++)
        #pragma unroll
        for (int b = 0; b < 8; b++)
            #pragma unroll
            for (int cix = 0; cix < 4; cix++) acc[a][b][cix] = 0.f;

    auto issue = [&](int c) {
        const int st = c & 1;
        const int k0 = c * 32;
        const uint32_t soff = (uint32_t)st * 20480;
        const __nv_bfloat16* gah = Abh + (size_t)(m0 + arow) * DD + k0 + aq * 16;
        const __nv_bfloat16* gal = Abl + (size_t)(m0 + arow) * DD + k0 + aq * 16;
        const __nv_bfloat16* gbh = Bbh + (size_t)(n0c + arow) * DD + k0 + aq * 16;
        const __nv_bfloat16* gbl = Bbl + (size_t)(n0c + arow) * DD + k0 + aq * 16;
        uint32_t da = sbase + (soff + arow * 40 + aq * 16) * 2;
        cp16(da,              gah,     16u);
        cp16(da + 16,         gah + 8, 16u);
        cp16(da + 5120 * 2,       gal,     16u);
        cp16(da + 5120 * 2 + 16,  gal + 8, 16u);
        cp16(da + 10240 * 2,      gbh,     16u);
        cp16(da + 10240 * 2 + 16, gbh + 8, 16u);
        cp16(da + 15360 * 2,      gbl,     16u);
        cp16(da + 15360 * 2 + 16, gbl + 8, 16u);
    };

    issue(0);
    asm volatile("cp.async.commit_group;");
    for (int c = 0; c < 2; c++) {
        if (c == 0) {
            issue(1);
            asm volatile("cp.async.commit_group;");
            asm volatile("cp.async.wait_group 1;");
        } else {
            asm volatile("cp.async.wait_group 0;");
        }
        __syncthreads();
        const uint32_t s0 = (uint32_t)(c & 1) * 20480;
        #pragma unroll
        for (int ks = 0; ks < 2; ks++) {
            const int kk = ks * 16 + tc * 2;
            uint32_t fah[2][4], fal[2][4];
            #pragma unroll
            for (int mt = 0; mt < 2; mt++) {
                int r = wm * 32 + mt * 16 + g;
                fah[mt][0] = *(const uint32_t*)&sm[s0 + r * 40 + kk];
                fah[mt][1] = *(const uint32_t*)&sm[s0 + (r + 8) * 40 + kk];
                fah[mt][2] = *(const uint32_t*)&sm[s0 + r * 40 + kk + 8];
                fah[mt][3] = *(const uint32_t*)&sm[s0 + (r + 8) * 40 + kk + 8];
                fal[mt][0] = *(const uint32_t*)&sm[s0 + 5120 + r * 40 + kk];
                fal[mt][1] = *(const uint32_t*)&sm[s0 + 5120 + (r + 8) * 40 + kk];
                fal[mt][2] = *(const uint32_t*)&sm[s0 + 5120 + r * 40 + kk + 8];
                fal[mt][3] = *(const uint32_t*)&sm[s0 + 5120 + (r + 8) * 40 + kk + 8];
            }
            #pragma unroll
            for (int nt = 0; nt < 8; nt++) {
                int n = wn * 64 + nt * 8 + g;
                uint32_t fbh[2], fbl[2];
                fbh[0] = *(const uint32_t*)&sm[s0 + 10240 + n * 40 + kk];
                fbh[1] = *(const uint32_t*)&sm[s0 + 10240 + n * 40 + kk + 8];
                fbl[0] = *(const uint32_t*)&sm[s0 + 15360 + n * 40 + kk];
                fbl[1] = *(const uint32_t*)&sm[s0 + 15360 + n * 40 + kk + 8];
                #pragma unroll
                for (int mt = 0; mt < 2; mt++) {
                    mma16816(acc[mt][nt], fah[mt], fbh);
                    mma16816(acc[mt][nt], fah[mt], fbl);
                    mma16816(acc[mt][nt], fal[mt], fbh);
                }
            }
        }
        __syncthreads();
    }

    float* Cb = C + (size_t)z * LL * Nn;
    #pragma unroll
    for (int mt = 0; mt < 2; mt++) {
        int r = m0 + wm * 32 + mt * 16 + g;
        #pragma unroll
        for (int nt = 0; nt < 8; nt++) {
            int cc = n0c + wn * 64 + nt * 8 + tc * 2;
            *(float2*)&Cb[(size_t)r * Nn + cc]       = make_float2(acc[mt][nt][0], acc[mt][nt][1]);
            *(float2*)&Cb[(size_t)(r + 8) * Nn + cc] = make_float2(acc[mt][nt][2], acc[mt][nt][3]);
        }
    }
}

// ================= per-head prep kernels =================
__global__ void qkprep(const float* __restrict__ rwb, const float* __restrict__ rrb) {
    int i = blockIdx.x * blockDim.x + threadIdx.x;
    if (i >= NB * LL * EE) return;
    int n = i / (LL * EE);
    int r2 = i % (LL * EE);
    int l = r2 / EE, e = r2 % EE;
    int h = e >> 6, d = e & 63;
    size_t o = ((size_t)(n * HH + h) * LL + l) * DD + d;
    float qv = g_q[i], kv = g_k[i];
    bsplit(qv + rwb[e], &g_qwh[o], &g_qwl[o]);
    bsplit(qv + rrb[e], &g_qrh[o], &g_qrl[o]);
    bsplit(kv,          &g_khh[o], &g_khl[o]);
}

__global__ void vtprep() {
    __shared__ float tile[64][65];
    int nh = blockIdx.x;
    int n = nh / HH, h = nh % HH;
    int l0 = blockIdx.y * 64;
    int t = threadIdx.x;
    for (int i = t; i < 4096; i += 256) {
        int l = i >> 6, d = i & 63;
        tile[l][d] = g_v[((size_t)(n * LL) + l0 + l) * EE + h * DD + d];
    }
    __syncthreads();
    for (int i = t; i < 4096; i += 256) {
        int d = i >> 6, l = i & 63;
        size_t o = ((size_t)nh * DD + d) * LL + l0 + l;
        bsplit(tile[l][d], &g_vth[o], &g_vtl[o]);
    }
}

__global__ void Rprep() {
    int i = blockIdx.x * blockDim.x + threadIdx.x;
    if (i >= HH * 1024 * DD) return;
    int h = i / (1024 * DD);
    int j = (i >> 6) & 1023;
    int d = i & 63;
    float v = (j < MPOS) ? g_R[(size_t)j * EE + h * DD + d] : 0.f;
    bsplit(v, &g_Rth[i], &g_Rtl[i]);
}

// ================= fused gather + softmax -> split-bf16 attn =================
__global__ void softmax_kernel() {
    int row  = blockIdx.x * 8 + (threadIdx.x >> 5);   // nh*512 + q
    int lane = threadIdx.x & 31;
    int q = row & (LL - 1);
    const float* ac = g_s  + (size_t)row * LL;
    const float* bd = g_bd + (size_t)row * 1024;
    float vals[16];
    float mx = -INFINITY;
    #pragma unroll
    for (int i = 0; i < 16; i++) {
        int k = lane + i * 32;
        vals[i] = (ac[k] + bd[q + 511 - k]) * 0.125f;
        mx = fmaxf(mx, vals[i]);
    }
    #pragma unroll
    for (int o = 16; o; o >>= 1) mx = fmaxf(mx, __shfl_xor_sync(0xffffffffu, mx, o));
    float sum = 0.f;
    #pragma unroll
    for (int i = 0; i < 16; i++) { vals[i] = __expf(vals[i] - mx); sum += vals[i]; }
    #pragma unroll
    for (int o = 16; o; o >>= 1) sum += __shfl_xor_sync(0xffffffffu, sum, o);
    float inv = 1.f / sum;
    __nv_bfloat16* ah = g_ath + (size_t)row * LL;
    __nv_bfloat16* al = g_atl + (size_t)row * LL;
    #pragma unroll
    for (int i = 0; i < 16; i++) {
        int k = lane + i * 32;
        bsplit(vals[i] * inv, &ah[k], &al[k]);
    }
}

// ================= AV batched MMA: out[z][512,64] = attn[z] @ vt[z]^T =================
// CTA 128x64, 8 warps (4 m x 2 n), warp tile 32x32, K=512 in 16 chunks of 32.
#define AVSMEM (2 * 15360 * 2)
__global__ __launch_bounds__(256) void av_mma() {
    extern __shared__ __nv_bfloat16 sm[];
    const uint32_t sbase = smem_to_u32(sm);
    const int t = threadIdx.x;
    const int lane = t & 31, wid = t >> 5;
    const int wm = wid & 3, wn = wid >> 2;
    const int z = blockIdx.y;
    const int n = z / HH, h = z % HH;
    const int m0 = blockIdx.x * 128;
    const int g = lane >> 2, tc = lane & 3;

    const __nv_bfloat16* Abh = g_ath + (size_t)z * LL * LL;
    const __nv_bfloat16* Abl = g_atl + (size_t)z * LL * LL;
    const __nv_bfloat16* Bbh = g_vth + (size_t)z * DD * LL;
    const __nv_bfloat16* Bbl = g_vtl + (size_t)z * DD * LL;

    const int arow = t >> 1, aq = t & 1;
    const int brow = t >> 2, bq = t & 3;

    float acc[2][4][4];
    #pragma unroll
    for (int a = 0; a < 2; a++)
        #pragma unroll
        for (int b = 0; b < 4; b++)
            #pragma unroll
            for (int cix = 0; cix < 4; cix++) acc[a][b][cix] = 0.f;

    auto issue = [&](int c) {
        const int st = c & 1;
        const int k0 = c * 32;
        const uint32_t soff = (uint32_t)st * 15360;
        const __nv_bfloat16* gah = Abh + (size_t)(m0 + arow) * LL + k0 + aq * 16;
        const __nv_bfloat16* gal = Abl + (size_t)(m0 + arow) * LL + k0 + aq * 16;
        uint32_t da = sbase + (soff + arow * 40 + aq * 16) * 2;
        cp16(da,             gah,     16u);
        cp16(da + 16,        gah + 8, 16u);
        cp16(da + 5120 * 2,      gal,     16u);
        cp16(da + 5120 * 2 + 16, gal + 8, 16u);
        const __nv_bfloat16* gbh = Bbh + (size_t)brow * LL + k0 + bq * 8;
        const __nv_bfloat16* gbl = Bbl + (size_t)brow * LL + k0 + bq * 8;
        uint32_t db = sbase + (soff + brow * 40 + bq * 8) * 2;
        cp16(db + 10240 * 2, gbh, 16u);
        cp16(db + 12800 * 2, gbl, 16u);
    };

    issue(0);
    asm volatile("cp.async.commit_group;");
    const int nk = LL / 32;  // 16
    for (int c = 0; c < nk; c++) {
        if (c + 1 < nk) {
            issue(c + 1);
            asm volatile("cp.async.commit_group;");
            asm volatile("cp.async.wait_group 1;");
        } else {
            asm volatile("cp.async.wait_group 0;");
        }
        __syncthreads();
        const uint32_t s0 = (uint32_t)(c & 1) * 15360;
        #pragma unroll
        for (int ks = 0; ks < 2; ks++) {
            const int kk = ks * 16 + tc * 2;
            uint32_t fah[2][4], fal[2][4];
            #pragma unroll
            for (int mt = 0; mt < 2; mt++) {
                int r = wm * 32 + mt * 16 + g;
                fah[mt][0] = *(const uint32_t*)&sm[s0 + r * 40 + kk];
                fah[mt][1] = *(const uint32_t*)&sm[s0 + (r + 8) * 40 + kk];
                fah[mt][2] = *(const uint32_t*)&sm[s0 + r * 40 + kk + 8];
                fah[mt][3] = *(const uint32_t*)&sm[s0 + (r + 8) * 40 + kk + 8];
                fal[mt][0] = *(const uint32_t*)&sm[s0 + 5120 + r * 40 + kk];
                fal[mt][1] = *(const uint32_t*)&sm[s0 + 5120 + (r + 8) * 40 + kk];
                fal[mt][2] = *(const uint32_t*)&sm[s0 + 5120 + r * 40 + kk + 8];
                fal[mt][3] = *(const uint32_t*)&sm[s0 + 5120 + (r + 8) * 40 + kk + 8];
            }
            #pragma unroll
            for (int nt = 0; nt < 4; nt++) {
                int nn = wn * 32 + nt * 8 + g;
                uint32_t fbh[2], fbl[2];
                fbh[0] = *(const uint32_t*)&sm[s0 + 10240 + nn * 40 + kk];
                fbh[1] = *(const uint32_t*)&sm[s0 + 10240 + nn * 40 + kk + 8];
                fbl[0] = *(const uint32_t*)&sm[s0 + 12800 + nn * 40 + kk];
                fbl[1] = *(const uint32_t*)&sm[s0 + 12800 + nn * 40 + kk + 8];
                #pragma unroll
                for (int mt = 0; mt < 2; mt++) {
                    mma16816(acc[mt][nt], fah[mt], fbh);
                    mma16816(acc[mt][nt], fah[mt], fbl);
                    mma16816(acc[mt][nt], fal[mt], fbh);
                }
            }
        }
        __syncthreads();
    }

    #pragma unroll
    for (int mt = 0; mt < 2; mt++) {
        int r = m0 + wm * 32 + mt * 16 + g;
        #pragma unroll
        for (int nt = 0; nt < 4; nt++) {
            int cc = wn * 32 + nt * 8 + tc * 2;
            float* dst0 = &g_o[((size_t)(n * LL) + r) * EE + h * DD + cc];
            float* dst1 = &g_o[((size_t)(n * LL) + r + 8) * EE + h * DD + cc];
            *(float2*)dst0 = make_float2(acc[mt][nt][0], acc[mt][nt][1]);
            *(float2*)dst1 = make_float2(acc[mt][nt][2], acc[mt][nt][3]);
        }
    }
}

// ================= launch =================
extern "C" void kernel_launch(void* const* d_in, const int* in_sizes, int n_in,
                              void* d_out, int out_size) {
    const float* values = (const float*)d_in[0];
    const float* keys   = (const float*)d_in[1];
    const float* query  = (const float*)d_in[2];
    const float* Wq = (const float*)d_in[3];
    const float* bq = (const float*)d_in[4];
    const float* Wk = (const float*)d_in[5];
    const float* bk = (const float*)d_in[6];
    const float* Wv = (const float*)d_in[7];
    const float* bv = (const float*)d_in[8];
    const float* Wo = (const float*)d_in[9];
    const float* bo = (const float*)d_in[10];
    const float* Wpos = (const float*)d_in[11];
    const float* bpos = (const float*)d_in[12];
    const float* rwb  = (const float*)d_in[13];
    const float* rrb  = (const float*)d_in[14];
    float* out = (float*)d_out;

    float* R_ptr;  cudaGetSymbolAddress((void**)&R_ptr,  g_R);
    float* q_ptr;  cudaGetSymbolAddress((void**)&q_ptr,  g_q);
    float* k_ptr;  cudaGetSymbolAddress((void**)&k_ptr,  g_k);
    float* v_ptr;  cudaGetSymbolAddress((void**)&v_ptr,  g_v);
    float* o_ptr;  cudaGetSymbolAddress((void**)&o_ptr,  g_o);
    float* s_ptr;  cudaGetSymbolAddress((void**)&s_ptr,  g_s);
    float* bd_ptr; cudaGetSymbolAddress((void**)&bd_ptr, g_bd);
    __nv_bfloat16 *Ah, *Al, *Bh, *Bl;
    cudaGetSymbolAddress((void**)&Ah, g_Ah);
    cudaGetSymbolAddress((void**)&Al, g_Al);
    cudaGetSymbolAddress((void**)&Bh, g_Bh);
    cudaGetSymbolAddress((void**)&Bl, g_Bl);
    __nv_bfloat16 *qwh, *qwl, *qrh, *qrl, *khh, *khl, *Rth, *Rtl;
    cudaGetSymbolAddress((void**)&qwh, g_qwh);
    cudaGetSymbolAddress((void**)&qwl, g_qwl);
    cudaGetSymbolAddress((void**)&qrh, g_qrh);
    cudaGetSymbolAddress((void**)&qrl, g_qrl);
    cudaGetSymbolAddress((void**)&khh, g_khh);
    cudaGetSymbolAddress((void**)&khl, g_khl);
    cudaGetSymbolAddress((void**)&Rth, g_Rth);
    cudaGetSymbolAddress((void**)&Rtl, g_Rtl);

    const int M = NB * LL;  // 4096
    static bool attr_set = false;
    if (!attr_set) {
        cudaFuncSetAttribute(gemm_mma, cudaFuncAttributeMaxDynamicSharedMemorySize, GSMEM);
        cudaFuncSetAttribute(bmma,     cudaFuncAttributeMaxDynamicSharedMemorySize, GSMEM);
        cudaFuncSetAttribute(av_mma,   cudaFuncAttributeMaxDynamicSharedMemorySize, AVSMEM);
        attr_set = true;
    }

    const dim3 tsg(24, 24), tsb(32, 8);
    const int splitN = M * EE;
    const int splitB = (splitN / 4 + 255) / 256;

    // R = pe @ Wpos + bpos
    pe_kernel<<<(MPOS * (EE / 2) + 255) / 256, 256>>>(Ah, Al);
    tsplit_kernel<<<tsg, tsb>>>(Wpos, Bh, Bl);
    gemm_mma<<<dim3(EE / 128, 8), 256, GSMEM>>>(Ah, Al, Bh, Bl, bpos, R_ptr, MPOS, EE, EE);

    // projections
    split_kernel<<<splitB, 256>>>(query, Ah, Al, splitN);
    tsplit_kernel<<<tsg, tsb>>>(Wq, Bh, Bl);
    gemm_mma<<<dim3(EE / 128, M / 128), 256, GSMEM>>>(Ah, Al, Bh, Bl, bq, q_ptr, M, EE, EE);

    split_kernel<<<splitB, 256>>>(keys, Ah, Al, splitN);
    tsplit_kernel<<<tsg, tsb>>>(Wk, Bh, Bl);
    gemm_mma<<<dim3(EE / 128, M / 128), 256, GSMEM>>>(Ah, Al, Bh, Bl, bk, k_ptr, M, EE, EE);

    split_kernel<<<splitB, 256>>>(values, Ah, Al, splitN);
    tsplit_kernel<<<tsg, tsb>>>(Wv, Bh, Bl);
    gemm_mma<<<dim3(EE / 128, M / 128), 256, GSMEM>>>(Ah, Al, Bh, Bl, bv, v_ptr, M, EE, EE);

    // per-head re-layout + splits
    qkprep<<<(NB * LL * EE + 255) / 256, 256>>>(rwb, rrb);
    vtprep<<<dim3(NHB, LL / 64), 256>>>();
    Rprep<<<(HH * 1024 * DD + 255) / 256, 256>>>();

    // scores: ac then bd
    bmma<<<dim3(4, 4, NHB), 256, GSMEM>>>(qwh, qwl, khh, khl, s_ptr, LL, 0);
    bmma<<<dim3(5, 4, NHB), 256, GSMEM>>>(qrh, qrl, Rth, Rtl, bd_ptr, 1024, 1);

    // fused gather + softmax -> split attn
    softmax_kernel<<<(NHB * LL) / 8, 256>>>();

    // attn @ v
    av_mma<<<dim3(LL / 128, NHB), 256, AVSMEM>>>();

    // output projection
    split_kernel<<<splitB, 256>>>(o_ptr, Ah, Al, splitN);
    tsplit_kernel<<<tsg, tsb>>>(Wo, Bh, Bl);
    gemm_mma<<<dim3(EE / 128, M / 128), 256, GSMEM>>>(Ah, Al, Bh, Bl, bo, out, M, EE, EE);
}